// round 13
// baseline (speedup 1.0000x reference)
#include <cuda_runtime.h>
#include <cuda_bf16.h>
#include <cuda_fp16.h>
#include <math.h>
#include <stdint.h>

#define NN    50000
#define DH    256
#define DOUT  128
#define EMAX  800000

// ---------------- scratch (device globals; referenced by symbol only) --------
__device__ __half g_h  [(size_t)NN * DH];        // GEMM output (fp16)
__device__ __nv_bfloat16 g_ah[(size_t)NN * DH];  // A split hi (GEMM input)
__device__ __nv_bfloat16 g_al[(size_t)NN * DH];  // A split lo
__device__ __nv_bfloat16 g_wth[2 * 65536 + 32768]; // W^T hi (3 layers, [m][k])
__device__ __nv_bfloat16 g_wtl[2 * 65536 + 32768]; // W^T lo
__device__ float g_dinv[NN];
__device__ int   g_cnt [NN];                     // zero-init; re-zeroed by k_scan
__device__ int   g_rowptr[NN + 1];
__device__ int   g_cursor[NN];
__device__ int2  g_csr [EMAX];                   // {src, w as int bits}
__device__ int   g_is64;

__device__ __forceinline__ uint32_t smem_u32(const void* p) {
    uint32_t a;
    asm("{ .reg .u64 t; cvta.to.shared.u64 t, %1; cvt.u32.u64 %0, t; }"
        : "=r"(a) : "l"(p));
    return a;
}

// ---------------- hi/lo split --------------------------------------------------
__device__ __forceinline__ void split1(float v, unsigned short& hb, unsigned short& lb) {
    __nv_bfloat16 h = __float2bfloat16(v);
    float hf = __bfloat162float(h);
    __nv_bfloat16 l = __float2bfloat16(v - hf);
    hb = reinterpret_cast<unsigned short&>(h);
    lb = reinterpret_cast<unsigned short&>(l);
}

__device__ __forceinline__ int clampi(int v) { return min(max(v, 0), NN - 1); }

// ---------------- fused edge-independent prep ---------------------------------
__global__ void k_prep0(const float* __restrict__ W1,
                        const float* __restrict__ W2,
                        const float* __restrict__ W3,
                        const float* __restrict__ x,
                        const void* __restrict__ ei, int n4, int E) {
    int i = blockIdx.x * blockDim.x + threadIdx.x;

    __shared__ int s_any;
    if (threadIdx.x == 0) s_any = 0;
    __syncthreads();
    {
        const int* ei32 = (const int*)ei;
        int a = 0;
        for (int k = threadIdx.x; k < 1024; k += blockDim.x)
            if (ei32[2 * k + 1] != 0) a = 1;
        if (a) atomicOr(&s_any, 1);
    }
    __syncthreads();
    const int is64 = s_any ? 0 : 1;
    if (i == 0) g_is64 = is64;

    if (i < n4) {
        float4 v = ((const float4*)x)[i];
        ushort4 hv, lv;
        split1(v.x, hv.x, lv.x);
        split1(v.y, hv.y, lv.y);
        split1(v.z, hv.z, lv.z);
        split1(v.w, hv.w, lv.w);
        ((ushort4*)g_ah)[i] = hv;
        ((ushort4*)g_al)[i] = lv;
    }
    if (i < 163840) {
        const float* W; int M, off, j = i;
        if (j < 65536)       { W = W1; M = DH;   off = 0;      }
        else if (j < 131072) { W = W2; M = DH;   off = 65536;  j -= 65536;  }
        else                 { W = W3; M = DOUT; off = 131072; j -= 131072; }
        int k = j / M, m = j % M;
        unsigned short hb, lb;
        split1(W[j], hb, lb);
        g_wth[off + (size_t)m * DH + k] = reinterpret_cast<__nv_bfloat16&>(hb);
        g_wtl[off + (size_t)m * DH + k] = reinterpret_cast<__nv_bfloat16&>(lb);
    }
    if (i < E) {
        int d;
        if (is64) d = (int)((const long long*)ei)[(size_t)E + i];
        else      d = ((const int*)ei)[(size_t)E + i];
        atomicAdd(&g_cnt[clampi(d)], 1);
    }
}

__device__ __forceinline__ int ld_idx(const void* ei, size_t pos) {
    int v;
    if (g_is64) v = (int)((const long long*)ei)[pos];
    else        v = ((const int*)ei)[pos];
    return clampi(v);
}

__global__ void k_scan() {
    const int T = 1024;
    __shared__ int part[T];
    int tid = threadIdx.x;
    int chunk = (NN + T - 1) / T;
    int base = tid * chunk;
    int sum = 0;
    for (int i = 0; i < chunk; i++) {
        int j = base + i;
        if (j < NN) {
            int c = g_cnt[j];
            sum += c;
            g_dinv[j] = rsqrtf(1.0f + (float)c);
        }
    }
    part[tid] = sum;
    __syncthreads();
    for (int off = 1; off < T; off <<= 1) {
        int v = (tid >= off) ? part[tid - off] : 0;
        __syncthreads();
        part[tid] += v;
        __syncthreads();
    }
    int run = (tid > 0) ? part[tid - 1] : 0;
    for (int i = 0; i < chunk; i++) {
        int j = base + i;
        if (j < NN) {
            int c = g_cnt[j];
            g_rowptr[j] = run;
            g_cursor[j] = run;
            g_cnt[j]    = 0;
            run += c;
        }
    }
    if (tid == T - 1) g_rowptr[NN] = run;
}

__global__ void k_fill(const void* __restrict__ ei, int E) {
    int e = blockIdx.x * blockDim.x + threadIdx.x;
    if (e < E) {
        int s = ld_idx(ei, (size_t)e);
        int d = ld_idx(ei, (size_t)E + e);
        int pos = atomicAdd(&g_cursor[d], 1);
        g_csr[pos] = make_int2(s, __float_as_int(g_dinv[s] * g_dinv[d]));
    }
}

// ---------------- mma.sync bf16 split GEMM: 128x64 tile, 3-stage chunk-16 -----
// smem stride 24 shorts (48B rows, conflict-free ldmatrix via (3r+c) mod 8).
#define SSTR   24
#define A_SH   (128 * SSTR)          // 3072 shorts per A array
#define B_SH   (64 * SSTR)           // 1536 shorts per B array
#define STG_SH (2 * A_SH + 2 * B_SH) // 9216 shorts per stage
#define STG_B  (STG_SH * 2)          // 18432 bytes
#define SMEM_B (3 * STG_B)           // 55296 bytes

__device__ __forceinline__ void ldsm_x4(uint32_t* r, uint32_t a) {
    asm volatile("ldmatrix.sync.aligned.m8n8.x4.shared.b16 {%0,%1,%2,%3}, [%4];"
                 : "=r"(r[0]), "=r"(r[1]), "=r"(r[2]), "=r"(r[3]) : "r"(a));
}
__device__ __forceinline__ void mma16816(float* d, const uint32_t* a, const uint32_t* b) {
    asm volatile(
        "mma.sync.aligned.m16n8k16.row.col.f32.bf16.bf16.f32 "
        "{%0,%1,%2,%3}, {%4,%5,%6,%7}, {%8,%9}, {%0,%1,%2,%3};"
        : "+f"(d[0]), "+f"(d[1]), "+f"(d[2]), "+f"(d[3])
        : "r"(a[0]), "r"(a[1]), "r"(a[2]), "r"(a[3]), "r"(b[0]), "r"(b[1]));
}
__device__ __forceinline__ void cp16(uint32_t d, const void* s, int sz) {
    asm volatile("cp.async.cg.shared.global [%0], [%1], 16, %2;"
                 :: "r"(d), "l"(s), "r"(sz));
}

__global__ __launch_bounds__(256, 3) void k_mgemm(int N, int M, int woff) {
    extern __shared__ __align__(16) unsigned short smem[];

    const int tid  = threadIdx.x;
    const int wid  = tid >> 5;
    const int lane = tid & 31;
    const int wm   = wid >> 1;          // 0..3 -> m rows wm*32
    const int wn   = wid & 1;           // 0..1 -> n cols wn*32
    const int row0 = blockIdx.x * 128;
    const int col0 = blockIdx.y * 64;

    float acc[2][4][4];
    #pragma unroll
    for (int i = 0; i < 2; i++)
        #pragma unroll
        for (int j = 0; j < 4; j++)
            #pragma unroll
            for (int q = 0; q < 4; q++) acc[i][j][q] = 0.f;

    const uint32_t sbase = smem_u32(smem);

    auto stage = [&](int sidx, int k0) {
        uint32_t b0 = sbase + (uint32_t)sidx * STG_B;
        {   // A hi/lo: 128 rows x 16 k -> 256 16B chunks per array
            int r = tid >> 1, v = tid & 1;
            uint32_t d = b0 + (uint32_t)(r * SSTR + v * 8) * 2;
            int row = row0 + r;
            int sz = (row < N) ? 16 : 0;
            size_t ga = (size_t)row * DH + k0 + v * 8;
            cp16(d,            &g_ah[ga], sz);
            cp16(d + A_SH * 2, &g_al[ga], sz);
        }
        if (tid < 128) {  // B hi/lo: 64 rows x 16 k
            int r = tid >> 1, v = tid & 1;
            uint32_t d = b0 + 2 * A_SH * 2 + (uint32_t)(r * SSTR + v * 8) * 2;
            size_t gb = (size_t)woff + (size_t)(col0 + r) * DH + k0 + v * 8;
            cp16(d,            &g_wth[gb], 16);
            cp16(d + B_SH * 2, &g_wtl[gb], 16);
        }
        asm volatile("cp.async.commit_group;");
    };

    const int NC = DH / 16;   // 16 chunks
    stage(0, 0);
    stage(1, 16);

    for (int c = 0; c < NC; c++) {
        if (c + 1 < NC) { asm volatile("cp.async.wait_group 1;"); }
        else            { asm volatile("cp.async.wait_group 0;"); }
        __syncthreads();                     // publish chunk c; safe to reuse buf (c+2)%3
        if (c + 2 < NC) stage((c + 2) % 3, (c + 2) * 16);

        uint32_t b0  = sbase + (uint32_t)(c % 3) * STG_B;
        uint32_t bAh = b0;
        uint32_t bAl = b0 + A_SH * 2;
        uint32_t bBh = b0 + 2 * A_SH * 2;
        uint32_t bBl = bBh + B_SH * 2;

        uint32_t ah[2][4], al[2][4];
        #pragma unroll
        for (int tm = 0; tm < 2; tm++) {
            int r = wm * 32 + tm * 16 + (lane & 15);
            uint32_t off = (uint32_t)(r * SSTR + (lane >> 4) * 8) * 2;
            ldsm_x4(ah[tm], bAh + off);
            ldsm_x4(al[tm], bAl + off);
        }
        #pragma unroll
        for (int tng = 0; tng < 4; tng += 2) {
            int r = wn * 32 + tng * 8 + (lane & 7) + ((lane >> 4) << 3);
            uint32_t off = (uint32_t)(r * SSTR + ((lane >> 3) & 1) * 8) * 2;
            uint32_t bh[4], bl[4];
            ldsm_x4(bh, bBh + off);
            ldsm_x4(bl, bBl + off);
            #pragma unroll
            for (int tm = 0; tm < 2; tm++) {
                mma16816(acc[tm][tng],     ah[tm], bh);
                mma16816(acc[tm][tng],     al[tm], bh);
                mma16816(acc[tm][tng],     ah[tm], bl);
                mma16816(acc[tm][tng + 1], ah[tm], bh + 2);
                mma16816(acc[tm][tng + 1], al[tm], bh + 2);
                mma16816(acc[tm][tng + 1], ah[tm], bl + 2);
            }
        }
    }

    // epilogue: fp32 acc -> fp16 g_h
    #pragma unroll
    for (int tm = 0; tm < 2; tm++) {
        int r0r = row0 + wm * 32 + tm * 16 + (lane >> 2);
        #pragma unroll
        for (int tn = 0; tn < 4; tn++) {
            int col = col0 + wn * 32 + tn * 8 + (lane & 3) * 2;
            if (r0r < N)
                *(__half2*)&g_h[(size_t)r0r * M + col] =
                    __floats2half2_rn(acc[tm][tn][0], acc[tm][tn][1]);
            if (r0r + 8 < N)
                *(__half2*)&g_h[(size_t)(r0r + 8) * M + col] =
                    __floats2half2_rn(acc[tm][tn][2], acc[tm][tn][3]);
        }
    }
}

// ---------------- aggregation (fp16 gather, MLP 8) + fused relu/split --------
__device__ __forceinline__ void h8f(uint4 v, float* f) {
    const __half2* p = reinterpret_cast<const __half2*>(&v);
    #pragma unroll
    for (int i = 0; i < 4; i++) {
        float2 t = __half22float2(p[i]);
        f[2 * i] = t.x; f[2 * i + 1] = t.y;
    }
}

__global__ __launch_bounds__(128) void k_agg(const float* __restrict__ bias,
                                             float* __restrict__ oext,
                                             int M, int mode)
{
    const int tpn  = M >> 3;
    const int node = blockIdx.x * (128 / tpn) + threadIdx.x / tpn;
    const int c    = threadIdx.x % tpn;
    const int rstr = M >> 3;

    const uint4* hb = (const uint4*)g_h;

    float di = g_dinv[node];
    float s  = di * di;
    float acc[8], tmp[8];
    h8f(hb[(size_t)node * rstr + c], tmp);
    float4 bv0 = *(const float4*)&bias[c * 8];
    float4 bv1 = *(const float4*)&bias[c * 8 + 4];
    acc[0] = fmaf(tmp[0], s, bv0.x); acc[1] = fmaf(tmp[1], s, bv0.y);
    acc[2] = fmaf(tmp[2], s, bv0.z); acc[3] = fmaf(tmp[3], s, bv0.w);
    acc[4] = fmaf(tmp[4], s, bv1.x); acc[5] = fmaf(tmp[5], s, bv1.y);
    acc[6] = fmaf(tmp[6], s, bv1.z); acc[7] = fmaf(tmp[7], s, bv1.w);

    int e   = g_rowptr[node];
    int end = g_rowptr[node + 1];

    for (; e + 7 < end; e += 8) {
        int2 p[8];
        #pragma unroll
        for (int j = 0; j < 8; j++) p[j] = g_csr[e + j];
        uint4 v[8];
        #pragma unroll
        for (int j = 0; j < 8; j++) v[j] = hb[(size_t)p[j].x * rstr + c];
        #pragma unroll
        for (int j = 0; j < 8; j++) {
            float w = __int_as_float(p[j].y);
            h8f(v[j], tmp);
            #pragma unroll
            for (int q = 0; q < 8; q++) acc[q] = fmaf(tmp[q], w, acc[q]);
        }
    }
    for (; e + 3 < end; e += 4) {
        int2 p[4];
        #pragma unroll
        for (int j = 0; j < 4; j++) p[j] = g_csr[e + j];
        uint4 v[4];
        #pragma unroll
        for (int j = 0; j < 4; j++) v[j] = hb[(size_t)p[j].x * rstr + c];
        #pragma unroll
        for (int j = 0; j < 4; j++) {
            float w = __int_as_float(p[j].y);
            h8f(v[j], tmp);
            #pragma unroll
            for (int q = 0; q < 8; q++) acc[q] = fmaf(tmp[q], w, acc[q]);
        }
    }
    for (; e < end; e++) {
        int2 p = g_csr[e];
        float w = __int_as_float(p.y);
        h8f(hb[(size_t)p.x * rstr + c], tmp);
        #pragma unroll
        for (int q = 0; q < 8; q++) acc[q] = fmaf(tmp[q], w, acc[q]);
    }

    if (mode == 0) {
        ushort4 hs0, hs1, ls0, ls1;
        #pragma unroll
        for (int j = 0; j < 8; j++) acc[j] = fmaxf(acc[j], 0.f);
        split1(acc[0], hs0.x, ls0.x); split1(acc[1], hs0.y, ls0.y);
        split1(acc[2], hs0.z, ls0.z); split1(acc[3], hs0.w, ls0.w);
        split1(acc[4], hs1.x, ls1.x); split1(acc[5], hs1.y, ls1.y);
        split1(acc[6], hs1.z, ls1.z); split1(acc[7], hs1.w, ls1.w);
        size_t o = (size_t)node * M + c * 8;
        *(ushort4*)&g_ah[o]     = hs0;
        *(ushort4*)&g_ah[o + 4] = hs1;
        *(ushort4*)&g_al[o]     = ls0;
        *(ushort4*)&g_al[o + 4] = ls1;
    } else {
        size_t o = (size_t)node * M + c * 8;
        *(float4*)&oext[o]     = make_float4(acc[0], acc[1], acc[2], acc[3]);
        *(float4*)&oext[o + 4] = make_float4(acc[4], acc[5], acc[6], acc[7]);
    }
}

// ---------------- launch -----------------------------------------------------
extern "C" void kernel_launch(void* const* d_in, const int* in_sizes, int n_in,
                              void* d_out, int out_size)
{
    const float* x  = (const float*)d_in[0];
    const void*  ei = d_in[1];
    const float* W1 = (const float*)d_in[2];
    const float* b1 = (const float*)d_in[3];
    const float* W2 = (const float*)d_in[4];
    const float* b2 = (const float*)d_in[5];
    const float* W3 = (const float*)d_in[6];
    const float* b3 = (const float*)d_in[7];
    float* out = (float*)d_out;

    const int N = NN;
    const int E = in_sizes[1] / 2;
    const int n4 = N * (DH / 4);

    cudaFuncSetAttribute(k_mgemm, cudaFuncAttributeMaxDynamicSharedMemorySize,
                         SMEM_B);

    dim3 tg_h((N + 127) / 128, DH / 64);     // 391 x 4
    dim3 tg_o((N + 127) / 128, DOUT / 64);   // 391 x 2

    k_prep0<<<(n4 + 255) / 256, 256>>>(W1, W2, W3, x, ei, n4, E);   // 0
    k_scan <<<1, 1024>>>();                                         // 1
    k_fill <<<(E + 255) / 256, 256>>>(ei, E);                       // 2

    k_mgemm<<<tg_h, 256, SMEM_B>>>(N, DH, 0);                       // 3
    k_agg  <<<NN / 4, 128>>>(b1, out, DH, 0);                       // 4

    k_mgemm<<<tg_h, 256, SMEM_B>>>(N, DH, 65536);                   // 5
    k_agg  <<<NN / 4, 128>>>(b2, out, DH, 0);                       // 6

    k_mgemm<<<tg_o, 256, SMEM_B>>>(N, DOUT, 131072);                // 7
    k_agg  <<<NN / 8, 128>>>(b3, out, DOUT, 1);                     // 8
}

// round 14
// speedup vs baseline: 1.1897x; 1.1897x over previous
#include <cuda_runtime.h>
#include <cuda_bf16.h>
#include <cuda_fp16.h>
#include <math.h>
#include <stdint.h>

#define NN    50000
#define DH    256
#define DOUT  128
#define EMAX  800000

// ---------------- scratch (device globals; referenced by symbol only) --------
__device__ __half g_h  [(size_t)NN * DH];        // GEMM output (fp16)
__device__ __nv_bfloat16 g_ah[(size_t)NN * DH];  // A split hi (GEMM input)
__device__ __nv_bfloat16 g_al[(size_t)NN * DH];  // A split lo
__device__ __nv_bfloat16 g_wth[2 * 65536 + 32768]; // W^T hi (3 layers, [m][k])
__device__ __nv_bfloat16 g_wtl[2 * 65536 + 32768]; // W^T lo
__device__ float g_dinv[NN];
__device__ int   g_cnt [NN];                     // zero-init; re-zeroed by k_scan
__device__ int   g_rowptr[NN + 1];
__device__ int   g_cursor[NN];
__device__ int2  g_csr [EMAX];                   // {src, w as int bits}
__device__ int   g_is64;

// side stream + fork/join events, created once at static init (not device mem)
static cudaStream_t g_side = nullptr;
static cudaEvent_t  g_ev_fork = nullptr, g_ev_join = nullptr;
namespace {
struct _StreamInit {
    _StreamInit() {
        cudaStreamCreateWithFlags(&g_side, cudaStreamNonBlocking);
        cudaEventCreateWithFlags(&g_ev_fork, cudaEventDisableTiming);
        cudaEventCreateWithFlags(&g_ev_join, cudaEventDisableTiming);
    }
} _stream_init;
}

__device__ __forceinline__ uint32_t smem_u32(const void* p) {
    uint32_t a;
    asm("{ .reg .u64 t; cvta.to.shared.u64 t, %1; cvt.u32.u64 %0, t; }"
        : "=r"(a) : "l"(p));
    return a;
}

// ---------------- hi/lo split --------------------------------------------------
__device__ __forceinline__ void split1(float v, unsigned short& hb, unsigned short& lb) {
    __nv_bfloat16 h = __float2bfloat16(v);
    float hf = __bfloat162float(h);
    __nv_bfloat16 l = __float2bfloat16(v - hf);
    hb = reinterpret_cast<unsigned short&>(h);
    lb = reinterpret_cast<unsigned short&>(l);
}

__device__ __forceinline__ int clampi(int v) { return min(max(v, 0), NN - 1); }

// ---------------- prepA: x split + weight split (feeds GEMM layer 1) ----------
__global__ void k_prepA(const float* __restrict__ W1,
                        const float* __restrict__ W2,
                        const float* __restrict__ W3,
                        const float* __restrict__ x, int n4) {
    int i = blockIdx.x * blockDim.x + threadIdx.x;
    if (i < n4) {
        float4 v = ((const float4*)x)[i];
        ushort4 hv, lv;
        split1(v.x, hv.x, lv.x);
        split1(v.y, hv.y, lv.y);
        split1(v.z, hv.z, lv.z);
        split1(v.w, hv.w, lv.w);
        ((ushort4*)g_ah)[i] = hv;
        ((ushort4*)g_al)[i] = lv;
    }
    if (i < 163840) {
        const float* W; int M, off, j = i;
        if (j < 65536)       { W = W1; M = DH;   off = 0;      }
        else if (j < 131072) { W = W2; M = DH;   off = 65536;  j -= 65536;  }
        else                 { W = W3; M = DOUT; off = 131072; j -= 131072; }
        int k = j / M, m = j % M;
        unsigned short hb, lb;
        split1(W[j], hb, lb);
        g_wth[off + (size_t)m * DH + k] = reinterpret_cast<__nv_bfloat16&>(hb);
        g_wtl[off + (size_t)m * DH + k] = reinterpret_cast<__nv_bfloat16&>(lb);
    }
}

// ---------------- prepB: dtype probe + degree count (side stream) -------------
__global__ void k_prepB(const void* __restrict__ ei, int E) {
    int i = blockIdx.x * blockDim.x + threadIdx.x;

    __shared__ int s_any;
    if (threadIdx.x == 0) s_any = 0;
    __syncthreads();
    {
        const int* ei32 = (const int*)ei;
        int a = 0;
        for (int k = threadIdx.x; k < 1024; k += blockDim.x)
            if (ei32[2 * k + 1] != 0) a = 1;
        if (a) atomicOr(&s_any, 1);
    }
    __syncthreads();
    const int is64 = s_any ? 0 : 1;
    if (i == 0) g_is64 = is64;

    if (i < E) {
        int d;
        if (is64) d = (int)((const long long*)ei)[(size_t)E + i];
        else      d = ((const int*)ei)[(size_t)E + i];
        atomicAdd(&g_cnt[clampi(d)], 1);
    }
}

__device__ __forceinline__ int ld_idx(const void* ei, size_t pos) {
    int v;
    if (g_is64) v = (int)((const long long*)ei)[pos];
    else        v = ((const int*)ei)[pos];
    return clampi(v);
}

__global__ void k_scan() {
    const int T = 1024;
    __shared__ int part[T];
    int tid = threadIdx.x;
    int chunk = (NN + T - 1) / T;
    int base = tid * chunk;
    int sum = 0;
    for (int i = 0; i < chunk; i++) {
        int j = base + i;
        if (j < NN) {
            int c = g_cnt[j];
            sum += c;
            g_dinv[j] = rsqrtf(1.0f + (float)c);
        }
    }
    part[tid] = sum;
    __syncthreads();
    for (int off = 1; off < T; off <<= 1) {
        int v = (tid >= off) ? part[tid - off] : 0;
        __syncthreads();
        part[tid] += v;
        __syncthreads();
    }
    int run = (tid > 0) ? part[tid - 1] : 0;
    for (int i = 0; i < chunk; i++) {
        int j = base + i;
        if (j < NN) {
            int c = g_cnt[j];
            g_rowptr[j] = run;
            g_cursor[j] = run;
            g_cnt[j]    = 0;
            run += c;
        }
    }
    if (tid == T - 1) g_rowptr[NN] = run;
}

__global__ void k_fill(const void* __restrict__ ei, int E) {
    int e = blockIdx.x * blockDim.x + threadIdx.x;
    if (e < E) {
        int s = ld_idx(ei, (size_t)e);
        int d = ld_idx(ei, (size_t)E + e);
        int pos = atomicAdd(&g_cursor[d], 1);
        g_csr[pos] = make_int2(s, __float_as_int(g_dinv[s] * g_dinv[d]));
    }
}

// ---------------- mma.sync bf16 split GEMM (R12 config) ------------------------
// 128x128 CTA tile, 8 warps (2x4), warp tile 64x32, K-chunk 32, 2-stage cp.async.
#define SSTR 40
#define BUFSH 20480

__device__ __forceinline__ void ldsm_x4(uint32_t& r0, uint32_t& r1,
                                        uint32_t& r2, uint32_t& r3, uint32_t a) {
    asm volatile("ldmatrix.sync.aligned.m8n8.x4.shared.b16 {%0,%1,%2,%3}, [%4];"
                 : "=r"(r0), "=r"(r1), "=r"(r2), "=r"(r3) : "r"(a));
}
__device__ __forceinline__ void mma16816(float* d, const uint32_t* a, const uint32_t* b) {
    asm volatile(
        "mma.sync.aligned.m16n8k16.row.col.f32.bf16.bf16.f32 "
        "{%0,%1,%2,%3}, {%4,%5,%6,%7}, {%8,%9}, {%0,%1,%2,%3};"
        : "+f"(d[0]), "+f"(d[1]), "+f"(d[2]), "+f"(d[3])
        : "r"(a[0]), "r"(a[1]), "r"(a[2]), "r"(a[3]), "r"(b[0]), "r"(b[1]));
}
__device__ __forceinline__ void cp16(uint32_t d, const void* s, int sz) {
    asm volatile("cp.async.cg.shared.global [%0], [%1], 16, %2;"
                 :: "r"(d), "l"(s), "r"(sz));
}

__global__ __launch_bounds__(256) void k_mgemm(int N, int M, int woff) {
    extern __shared__ __align__(16) unsigned short smem[];

    const int tid = threadIdx.x;
    const int wid = tid >> 5;
    const int lane = tid & 31;
    const int wm = wid >> 2;
    const int wn = wid & 3;
    const int row0 = blockIdx.x * 128;
    const int col0 = blockIdx.y * 128;

    float acc[4][4][4];
    #pragma unroll
    for (int i = 0; i < 4; i++)
        #pragma unroll
        for (int j = 0; j < 4; j++)
            #pragma unroll
            for (int q = 0; q < 4; q++) acc[i][j][q] = 0.f;

    const uint32_t sbase = smem_u32(smem);

    auto stage = [&](int buf, int k0) {
        uint32_t b0 = sbase + (uint32_t)buf * (BUFSH * 2);
        #pragma unroll
        for (int l = 0; l < 2; l++) {
            int idx = tid + l * 256;
            int r = idx >> 2, v = idx & 3;
            uint32_t d = b0 + (uint32_t)(r * SSTR + v * 8) * 2;
            int row = row0 + r;
            int sz = (row < N) ? 16 : 0;
            size_t ga = (size_t)row * DH + k0 + v * 8;
            cp16(d,             &g_ah[ga], sz);
            cp16(d + 5120 * 2,  &g_al[ga], sz);
            size_t gb = (size_t)woff + (size_t)(col0 + r) * DH + k0 + v * 8;
            cp16(d + 10240 * 2, &g_wth[gb], 16);
            cp16(d + 15360 * 2, &g_wtl[gb], 16);
        }
        asm volatile("cp.async.commit_group;");
    };

    stage(0, 0);

    for (int c = 0; c < 8; c++) {
        int buf = c & 1;
        if (c < 7) {
            stage(buf ^ 1, (c + 1) * 32);
            asm volatile("cp.async.wait_group 1;");
        } else {
            asm volatile("cp.async.wait_group 0;");
        }
        __syncthreads();

        uint32_t bAh = sbase + (uint32_t)buf * (BUFSH * 2);
        uint32_t bAl = bAh + 5120 * 2;
        uint32_t bBh = bAh + 10240 * 2;
        uint32_t bBl = bAh + 15360 * 2;

        #pragma unroll
        for (int kk = 0; kk < 32; kk += 16) {
            uint32_t ah[4][4], al[4][4];
            #pragma unroll
            for (int tm = 0; tm < 4; tm++) {
                int r = wm * 64 + tm * 16 + (lane & 15);
                uint32_t off = (uint32_t)(r * SSTR + kk + (lane >> 4) * 8) * 2;
                ldsm_x4(ah[tm][0], ah[tm][1], ah[tm][2], ah[tm][3], bAh + off);
                ldsm_x4(al[tm][0], al[tm][1], al[tm][2], al[tm][3], bAl + off);
            }
            // B: one x4 covers two n-tiles (lanes 16-31 -> rows +8)
            #pragma unroll
            for (int tn = 0; tn < 4; tn += 2) {
                int r = wn * 32 + tn * 8 + (lane & 7) + ((lane >> 4) << 3);
                uint32_t off = (uint32_t)(r * SSTR + kk + ((lane >> 3) & 1) * 8) * 2;
                uint32_t bh[4], bl[4];
                ldsm_x4(bh[0], bh[1], bh[2], bh[3], bBh + off);
                ldsm_x4(bl[0], bl[1], bl[2], bl[3], bBl + off);
                #pragma unroll
                for (int tm = 0; tm < 4; tm++) {
                    mma16816(acc[tm][tn],     ah[tm], bh);
                    mma16816(acc[tm][tn],     al[tm], bh);
                    mma16816(acc[tm][tn],     ah[tm], bl);
                    mma16816(acc[tm][tn + 1], ah[tm], bh + 2);
                    mma16816(acc[tm][tn + 1], al[tm], bh + 2);
                    mma16816(acc[tm][tn + 1], ah[tm], bl + 2);
                }
            }
        }
        __syncthreads();
    }

    // epilogue: fp32 acc -> fp16 g_h
    #pragma unroll
    for (int tm = 0; tm < 4; tm++) {
        int r0r = row0 + wm * 64 + tm * 16 + (lane >> 2);
        #pragma unroll
        for (int tn = 0; tn < 4; tn++) {
            int col = col0 + wn * 32 + tn * 8 + (lane & 3) * 2;
            if (r0r < N)
                *(__half2*)&g_h[(size_t)r0r * M + col] =
                    __floats2half2_rn(acc[tm][tn][0], acc[tm][tn][1]);
            if (r0r + 8 < N)
                *(__half2*)&g_h[(size_t)(r0r + 8) * M + col] =
                    __floats2half2_rn(acc[tm][tn][2], acc[tm][tn][3]);
        }
    }
}

// ---------------- aggregation (fp16 gather, MLP 8) + fused relu/split --------
__device__ __forceinline__ void h8f(uint4 v, float* f) {
    const __half2* p = reinterpret_cast<const __half2*>(&v);
    #pragma unroll
    for (int i = 0; i < 4; i++) {
        float2 t = __half22float2(p[i]);
        f[2 * i] = t.x; f[2 * i + 1] = t.y;
    }
}

__global__ __launch_bounds__(128) void k_agg(const float* __restrict__ bias,
                                             float* __restrict__ oext,
                                             int M, int mode)
{
    const int tpn  = M >> 3;
    const int node = blockIdx.x * (128 / tpn) + threadIdx.x / tpn;
    const int c    = threadIdx.x % tpn;
    const int rstr = M >> 3;

    const uint4* hb = (const uint4*)g_h;

    float di = g_dinv[node];
    float s  = di * di;
    float acc[8], tmp[8];
    h8f(hb[(size_t)node * rstr + c], tmp);
    float4 bv0 = *(const float4*)&bias[c * 8];
    float4 bv1 = *(const float4*)&bias[c * 8 + 4];
    acc[0] = fmaf(tmp[0], s, bv0.x); acc[1] = fmaf(tmp[1], s, bv0.y);
    acc[2] = fmaf(tmp[2], s, bv0.z); acc[3] = fmaf(tmp[3], s, bv0.w);
    acc[4] = fmaf(tmp[4], s, bv1.x); acc[5] = fmaf(tmp[5], s, bv1.y);
    acc[6] = fmaf(tmp[6], s, bv1.z); acc[7] = fmaf(tmp[7], s, bv1.w);

    int e   = g_rowptr[node];
    int end = g_rowptr[node + 1];

    for (; e + 7 < end; e += 8) {
        int2 p[8];
        #pragma unroll
        for (int j = 0; j < 8; j++) p[j] = g_csr[e + j];
        uint4 v[8];
        #pragma unroll
        for (int j = 0; j < 8; j++) v[j] = hb[(size_t)p[j].x * rstr + c];
        #pragma unroll
        for (int j = 0; j < 8; j++) {
            float w = __int_as_float(p[j].y);
            h8f(v[j], tmp);
            #pragma unroll
            for (int q = 0; q < 8; q++) acc[q] = fmaf(tmp[q], w, acc[q]);
        }
    }
    for (; e + 3 < end; e += 4) {
        int2 p[4];
        #pragma unroll
        for (int j = 0; j < 4; j++) p[j] = g_csr[e + j];
        uint4 v[4];
        #pragma unroll
        for (int j = 0; j < 4; j++) v[j] = hb[(size_t)p[j].x * rstr + c];
        #pragma unroll
        for (int j = 0; j < 4; j++) {
            float w = __int_as_float(p[j].y);
            h8f(v[j], tmp);
            #pragma unroll
            for (int q = 0; q < 8; q++) acc[q] = fmaf(tmp[q], w, acc[q]);
        }
    }
    for (; e < end; e++) {
        int2 p = g_csr[e];
        float w = __int_as_float(p.y);
        h8f(hb[(size_t)p.x * rstr + c], tmp);
        #pragma unroll
        for (int q = 0; q < 8; q++) acc[q] = fmaf(tmp[q], w, acc[q]);
    }

    if (mode == 0) {
        ushort4 hs0, hs1, ls0, ls1;
        #pragma unroll
        for (int j = 0; j < 8; j++) acc[j] = fmaxf(acc[j], 0.f);
        split1(acc[0], hs0.x, ls0.x); split1(acc[1], hs0.y, ls0.y);
        split1(acc[2], hs0.z, ls0.z); split1(acc[3], hs0.w, ls0.w);
        split1(acc[4], hs1.x, ls1.x); split1(acc[5], hs1.y, ls1.y);
        split1(acc[6], hs1.z, ls1.z); split1(acc[7], hs1.w, ls1.w);
        size_t o = (size_t)node * M + c * 8;
        *(ushort4*)&g_ah[o]     = hs0;
        *(ushort4*)&g_ah[o + 4] = hs1;
        *(ushort4*)&g_al[o]     = ls0;
        *(ushort4*)&g_al[o + 4] = ls1;
    } else {
        size_t o = (size_t)node * M + c * 8;
        *(float4*)&oext[o]     = make_float4(acc[0], acc[1], acc[2], acc[3]);
        *(float4*)&oext[o + 4] = make_float4(acc[4], acc[5], acc[6], acc[7]);
    }
}

// ---------------- launch -----------------------------------------------------
extern "C" void kernel_launch(void* const* d_in, const int* in_sizes, int n_in,
                              void* d_out, int out_size)
{
    const float* x  = (const float*)d_in[0];
    const void*  ei = d_in[1];
    const float* W1 = (const float*)d_in[2];
    const float* b1 = (const float*)d_in[3];
    const float* W2 = (const float*)d_in[4];
    const float* b2 = (const float*)d_in[5];
    const float* W3 = (const float*)d_in[6];
    const float* b3 = (const float*)d_in[7];
    float* out = (float*)d_out;

    const int N = NN;
    const int E = in_sizes[1] / 2;
    const int n4 = N * (DH / 4);
    const int SM_BYTES = 2 * BUFSH * 2;   // 81920

    cudaFuncSetAttribute(k_mgemm, cudaFuncAttributeMaxDynamicSharedMemorySize,
                         SM_BYTES);

    dim3 tg_h((N + 127) / 128, DH / 128);    // 391 x 2
    dim3 tg_o((N + 127) / 128, DOUT / 128);  // 391 x 1

    const bool par = (g_side != nullptr) && (g_ev_fork != nullptr)
                  && (g_ev_join != nullptr);

    if (par) {
        // fork: CSR chain on side stream, GEMM-feeding prep on main stream
        cudaEventRecord(g_ev_fork, 0);
        cudaStreamWaitEvent(g_side, g_ev_fork, 0);

        k_prepB<<<(E + 255) / 256, 256, 0, g_side>>>(ei, E);
        k_scan <<<1, 1024, 0, g_side>>>();
        k_fill <<<(E + 255) / 256, 256, 0, g_side>>>(ei, E);
        cudaEventRecord(g_ev_join, g_side);

        k_prepA<<<(n4 + 255) / 256, 256>>>(W1, W2, W3, x, n4);
        k_mgemm<<<tg_h, 256, SM_BYTES>>>(N, DH, 0);

        // join: agg needs rowptr/csr/dinv from side chain
        cudaStreamWaitEvent(0, g_ev_join, 0);
    } else {
        // serial fallback
        k_prepA<<<(n4 + 255) / 256, 256>>>(W1, W2, W3, x, n4);
        k_prepB<<<(E + 255) / 256, 256>>>(ei, E);
        k_scan <<<1, 1024>>>();
        k_fill <<<(E + 255) / 256, 256>>>(ei, E);
        k_mgemm<<<tg_h, 256, SM_BYTES>>>(N, DH, 0);
    }

    k_agg  <<<NN / 4, 128>>>(b1, out, DH, 0);

    k_mgemm<<<tg_h, 256, SM_BYTES>>>(N, DH, 65536);
    k_agg  <<<NN / 4, 128>>>(b2, out, DH, 0);

    k_mgemm<<<tg_o, 256, SM_BYTES>>>(N, DOUT, 131072);
    k_agg  <<<NN / 8, 128>>>(b3, out, DOUT, 1);
}

// round 15
// speedup vs baseline: 1.2818x; 1.0773x over previous
#include <cuda_runtime.h>
#include <cuda_bf16.h>
#include <cuda_fp16.h>
#include <math.h>
#include <stdint.h>

#define NN    50000
#define DH    256
#define DOUT  128
#define EMAX  800000

// ---------------- scratch (device globals; referenced by symbol only) --------
__device__ __half g_h  [(size_t)NN * DH];        // GEMM output (fp16)
__device__ __half g_ah [(size_t)NN * DH];        // A split hi (fp16)
__device__ __half g_al [(size_t)NN * DH];        // A split lo (fp16)
__device__ __half g_wh [2 * 65536 + 32768];      // W^T fp16 (3 layers, [m][k])
__device__ float g_dinv[NN];
__device__ int   g_cnt [NN];                     // zero-init; re-zeroed by k_scan
__device__ int   g_rowptr[NN + 1];
__device__ int   g_cursor[NN];
__device__ int2  g_csr [EMAX];                   // {src, w as int bits}
__device__ int   g_is64;

// side stream + fork/join events, created once at static init (not device mem)
static cudaStream_t g_side = nullptr;
static cudaEvent_t  g_ev_fork = nullptr, g_ev_join = nullptr;
namespace {
struct _StreamInit {
    _StreamInit() {
        cudaStreamCreateWithFlags(&g_side, cudaStreamNonBlocking);
        cudaEventCreateWithFlags(&g_ev_fork, cudaEventDisableTiming);
        cudaEventCreateWithFlags(&g_ev_join, cudaEventDisableTiming);
    }
} _stream_init;
}

__device__ __forceinline__ uint32_t smem_u32(const void* p) {
    uint32_t a;
    asm("{ .reg .u64 t; cvta.to.shared.u64 t, %1; cvt.u32.u64 %0, t; }"
        : "=r"(a) : "l"(p));
    return a;
}

// ---------------- fp16 hi/lo split ---------------------------------------------
__device__ __forceinline__ void split1h(float v, unsigned short& hb, unsigned short& lb) {
    __half h = __float2half_rn(v);
    float hf = __half2float(h);
    __half l = __float2half_rn(v - hf);
    hb = reinterpret_cast<unsigned short&>(h);
    lb = reinterpret_cast<unsigned short&>(l);
}

__device__ __forceinline__ int clampi(int v) { return min(max(v, 0), NN - 1); }

// ---------------- prepA: x split (fp16 hi/lo) + W fp16 (feeds GEMM layer 1) ---
__global__ void k_prepA(const float* __restrict__ W1,
                        const float* __restrict__ W2,
                        const float* __restrict__ W3,
                        const float* __restrict__ x, int n4) {
    int i = blockIdx.x * blockDim.x + threadIdx.x;
    if (i < n4) {
        float4 v = ((const float4*)x)[i];
        ushort4 hv, lv;
        split1h(v.x, hv.x, lv.x);
        split1h(v.y, hv.y, lv.y);
        split1h(v.z, hv.z, lv.z);
        split1h(v.w, hv.w, lv.w);
        ((ushort4*)g_ah)[i] = hv;
        ((ushort4*)g_al)[i] = lv;
    }
    if (i < 163840) {
        const float* W; int M, off, j = i;
        if (j < 65536)       { W = W1; M = DH;   off = 0;      }
        else if (j < 131072) { W = W2; M = DH;   off = 65536;  j -= 65536;  }
        else                 { W = W3; M = DOUT; off = 131072; j -= 131072; }
        int k = j / M, m = j % M;
        g_wh[off + (size_t)m * DH + k] = __float2half_rn(W[j]);
    }
}

// ---------------- prepB: dtype probe + degree count (side stream) -------------
__global__ void k_prepB(const void* __restrict__ ei, int E) {
    int i = blockIdx.x * blockDim.x + threadIdx.x;

    __shared__ int s_any;
    if (threadIdx.x == 0) s_any = 0;
    __syncthreads();
    {
        const int* ei32 = (const int*)ei;
        int a = 0;
        for (int k = threadIdx.x; k < 1024; k += blockDim.x)
            if (ei32[2 * k + 1] != 0) a = 1;
        if (a) atomicOr(&s_any, 1);
    }
    __syncthreads();
    const int is64 = s_any ? 0 : 1;
    if (i == 0) g_is64 = is64;

    if (i < E) {
        int d;
        if (is64) d = (int)((const long long*)ei)[(size_t)E + i];
        else      d = ((const int*)ei)[(size_t)E + i];
        atomicAdd(&g_cnt[clampi(d)], 1);
    }
}

__device__ __forceinline__ int ld_idx(const void* ei, size_t pos) {
    int v;
    if (g_is64) v = (int)((const long long*)ei)[pos];
    else        v = ((const int*)ei)[pos];
    return clampi(v);
}

__global__ void k_scan() {
    const int T = 1024;
    __shared__ int part[T];
    int tid = threadIdx.x;
    int chunk = (NN + T - 1) / T;
    int base = tid * chunk;
    int sum = 0;
    for (int i = 0; i < chunk; i++) {
        int j = base + i;
        if (j < NN) {
            int c = g_cnt[j];
            sum += c;
            g_dinv[j] = rsqrtf(1.0f + (float)c);
        }
    }
    part[tid] = sum;
    __syncthreads();
    for (int off = 1; off < T; off <<= 1) {
        int v = (tid >= off) ? part[tid - off] : 0;
        __syncthreads();
        part[tid] += v;
        __syncthreads();
    }
    int run = (tid > 0) ? part[tid - 1] : 0;
    for (int i = 0; i < chunk; i++) {
        int j = base + i;
        if (j < NN) {
            int c = g_cnt[j];
            g_rowptr[j] = run;
            g_cursor[j] = run;
            g_cnt[j]    = 0;
            run += c;
        }
    }
    if (tid == T - 1) g_rowptr[NN] = run;
}

__global__ void k_fill(const void* __restrict__ ei, int E) {
    int e = blockIdx.x * blockDim.x + threadIdx.x;
    if (e < E) {
        int s = ld_idx(ei, (size_t)e);
        int d = ld_idx(ei, (size_t)E + e);
        int pos = atomicAdd(&g_cursor[d], 1);
        g_csr[pos] = make_int2(s, __float_as_int(g_dinv[s] * g_dinv[d]));
    }
}

// ---------------- mma.sync fp16 2-term GEMM -----------------------------------
// 128x128 CTA tile, 8 warps (2x4), warp tile 64x32, K-chunk 32, 2-stage cp.async.
// smem: 3 arrays (Ah, Al, Wh) of 5120 shorts per stage.
#define SSTR 40
#define BUFSH 15360

__device__ __forceinline__ void ldsm_x4(uint32_t& r0, uint32_t& r1,
                                        uint32_t& r2, uint32_t& r3, uint32_t a) {
    asm volatile("ldmatrix.sync.aligned.m8n8.x4.shared.b16 {%0,%1,%2,%3}, [%4];"
                 : "=r"(r0), "=r"(r1), "=r"(r2), "=r"(r3) : "r"(a));
}
__device__ __forceinline__ void mma16816(float* d, const uint32_t* a, const uint32_t* b) {
    asm volatile(
        "mma.sync.aligned.m16n8k16.row.col.f32.f16.f16.f32 "
        "{%0,%1,%2,%3}, {%4,%5,%6,%7}, {%8,%9}, {%0,%1,%2,%3};"
        : "+f"(d[0]), "+f"(d[1]), "+f"(d[2]), "+f"(d[3])
        : "r"(a[0]), "r"(a[1]), "r"(a[2]), "r"(a[3]), "r"(b[0]), "r"(b[1]));
}
__device__ __forceinline__ void cp16(uint32_t d, const void* s, int sz) {
    asm volatile("cp.async.cg.shared.global [%0], [%1], 16, %2;"
                 :: "r"(d), "l"(s), "r"(sz));
}

__global__ __launch_bounds__(256) void k_mgemm(int N, int M, int woff) {
    extern __shared__ __align__(16) unsigned short smem[];

    const int tid = threadIdx.x;
    const int wid = tid >> 5;
    const int lane = tid & 31;
    const int wm = wid >> 2;
    const int wn = wid & 3;
    const int row0 = blockIdx.x * 128;
    const int col0 = blockIdx.y * 128;

    float acc[4][4][4];
    #pragma unroll
    for (int i = 0; i < 4; i++)
        #pragma unroll
        for (int j = 0; j < 4; j++)
            #pragma unroll
            for (int q = 0; q < 4; q++) acc[i][j][q] = 0.f;

    const uint32_t sbase = smem_u32(smem);

    auto stage = [&](int buf, int k0) {
        uint32_t b0 = sbase + (uint32_t)buf * (BUFSH * 2);
        #pragma unroll
        for (int l = 0; l < 2; l++) {
            int idx = tid + l * 256;
            int r = idx >> 2, v = idx & 3;
            uint32_t d = b0 + (uint32_t)(r * SSTR + v * 8) * 2;
            int row = row0 + r;
            int sz = (row < N) ? 16 : 0;
            size_t ga = (size_t)row * DH + k0 + v * 8;
            cp16(d,             &g_ah[ga], sz);
            cp16(d + 5120 * 2,  &g_al[ga], sz);
            size_t gb = (size_t)woff + (size_t)(col0 + r) * DH + k0 + v * 8;
            cp16(d + 10240 * 2, &g_wh[gb], 16);
        }
        asm volatile("cp.async.commit_group;");
    };

    stage(0, 0);

    for (int c = 0; c < 8; c++) {
        int buf = c & 1;
        if (c < 7) {
            stage(buf ^ 1, (c + 1) * 32);
            asm volatile("cp.async.wait_group 1;");
        } else {
            asm volatile("cp.async.wait_group 0;");
        }
        __syncthreads();

        uint32_t bAh = sbase + (uint32_t)buf * (BUFSH * 2);
        uint32_t bAl = bAh + 5120 * 2;
        uint32_t bBh = bAh + 10240 * 2;

        #pragma unroll
        for (int kk = 0; kk < 32; kk += 16) {
            uint32_t ah[4][4], al[4][4];
            #pragma unroll
            for (int tm = 0; tm < 4; tm++) {
                int r = wm * 64 + tm * 16 + (lane & 15);
                uint32_t off = (uint32_t)(r * SSTR + kk + (lane >> 4) * 8) * 2;
                ldsm_x4(ah[tm][0], ah[tm][1], ah[tm][2], ah[tm][3], bAh + off);
                ldsm_x4(al[tm][0], al[tm][1], al[tm][2], al[tm][3], bAl + off);
            }
            // B: one x4 covers two n-tiles (lanes 16-31 -> rows +8)
            #pragma unroll
            for (int tn = 0; tn < 4; tn += 2) {
                int r = wn * 32 + tn * 8 + (lane & 7) + ((lane >> 4) << 3);
                uint32_t off = (uint32_t)(r * SSTR + kk + ((lane >> 3) & 1) * 8) * 2;
                uint32_t bh[4];
                ldsm_x4(bh[0], bh[1], bh[2], bh[3], bBh + off);
                #pragma unroll
                for (int tm = 0; tm < 4; tm++) {
                    mma16816(acc[tm][tn],     ah[tm], bh);
                    mma16816(acc[tm][tn],     al[tm], bh);
                    mma16816(acc[tm][tn + 1], ah[tm], bh + 2);
                    mma16816(acc[tm][tn + 1], al[tm], bh + 2);
                }
            }
        }
        __syncthreads();
    }

    // epilogue: fp32 acc -> fp16 g_h
    #pragma unroll
    for (int tm = 0; tm < 4; tm++) {
        int r0r = row0 + wm * 64 + tm * 16 + (lane >> 2);
        #pragma unroll
        for (int tn = 0; tn < 4; tn++) {
            int col = col0 + wn * 32 + tn * 8 + (lane & 3) * 2;
            if (r0r < N)
                *(__half2*)&g_h[(size_t)r0r * M + col] =
                    __floats2half2_rn(acc[tm][tn][0], acc[tm][tn][1]);
            if (r0r + 8 < N)
                *(__half2*)&g_h[(size_t)(r0r + 8) * M + col] =
                    __floats2half2_rn(acc[tm][tn][2], acc[tm][tn][3]);
        }
    }
}

// ---------------- aggregation (fp16 gather, MLP 8) + fused relu/split --------
__device__ __forceinline__ void h8f(uint4 v, float* f) {
    const __half2* p = reinterpret_cast<const __half2*>(&v);
    #pragma unroll
    for (int i = 0; i < 4; i++) {
        float2 t = __half22float2(p[i]);
        f[2 * i] = t.x; f[2 * i + 1] = t.y;
    }
}

__global__ __launch_bounds__(128) void k_agg(const float* __restrict__ bias,
                                             float* __restrict__ oext,
                                             int M, int mode)
{
    const int tpn  = M >> 3;
    const int node = blockIdx.x * (128 / tpn) + threadIdx.x / tpn;
    const int c    = threadIdx.x % tpn;
    const int rstr = M >> 3;

    const uint4* hb = (const uint4*)g_h;

    float di = g_dinv[node];
    float s  = di * di;
    float acc[8], tmp[8];
    h8f(hb[(size_t)node * rstr + c], tmp);
    float4 bv0 = *(const float4*)&bias[c * 8];
    float4 bv1 = *(const float4*)&bias[c * 8 + 4];
    acc[0] = fmaf(tmp[0], s, bv0.x); acc[1] = fmaf(tmp[1], s, bv0.y);
    acc[2] = fmaf(tmp[2], s, bv0.z); acc[3] = fmaf(tmp[3], s, bv0.w);
    acc[4] = fmaf(tmp[4], s, bv1.x); acc[5] = fmaf(tmp[5], s, bv1.y);
    acc[6] = fmaf(tmp[6], s, bv1.z); acc[7] = fmaf(tmp[7], s, bv1.w);

    int e   = g_rowptr[node];
    int end = g_rowptr[node + 1];

    for (; e + 7 < end; e += 8) {
        int2 p[8];
        #pragma unroll
        for (int j = 0; j < 8; j++) p[j] = g_csr[e + j];
        uint4 v[8];
        #pragma unroll
        for (int j = 0; j < 8; j++) v[j] = hb[(size_t)p[j].x * rstr + c];
        #pragma unroll
        for (int j = 0; j < 8; j++) {
            float w = __int_as_float(p[j].y);
            h8f(v[j], tmp);
            #pragma unroll
            for (int q = 0; q < 8; q++) acc[q] = fmaf(tmp[q], w, acc[q]);
        }
    }
    for (; e + 3 < end; e += 4) {
        int2 p[4];
        #pragma unroll
        for (int j = 0; j < 4; j++) p[j] = g_csr[e + j];
        uint4 v[4];
        #pragma unroll
        for (int j = 0; j < 4; j++) v[j] = hb[(size_t)p[j].x * rstr + c];
        #pragma unroll
        for (int j = 0; j < 4; j++) {
            float w = __int_as_float(p[j].y);
            h8f(v[j], tmp);
            #pragma unroll
            for (int q = 0; q < 8; q++) acc[q] = fmaf(tmp[q], w, acc[q]);
        }
    }
    for (; e < end; e++) {
        int2 p = g_csr[e];
        float w = __int_as_float(p.y);
        h8f(hb[(size_t)p.x * rstr + c], tmp);
        #pragma unroll
        for (int q = 0; q < 8; q++) acc[q] = fmaf(tmp[q], w, acc[q]);
    }

    if (mode == 0) {
        ushort4 hs0, hs1, ls0, ls1;
        #pragma unroll
        for (int j = 0; j < 8; j++) acc[j] = fmaxf(acc[j], 0.f);
        split1h(acc[0], hs0.x, ls0.x); split1h(acc[1], hs0.y, ls0.y);
        split1h(acc[2], hs0.z, ls0.z); split1h(acc[3], hs0.w, ls0.w);
        split1h(acc[4], hs1.x, ls1.x); split1h(acc[5], hs1.y, ls1.y);
        split1h(acc[6], hs1.z, ls1.z); split1h(acc[7], hs1.w, ls1.w);
        size_t o = (size_t)node * M + c * 8;
        *(ushort4*)&g_ah[o]     = hs0;
        *(ushort4*)&g_ah[o + 4] = hs1;
        *(ushort4*)&g_al[o]     = ls0;
        *(ushort4*)&g_al[o + 4] = ls1;
    } else {
        size_t o = (size_t)node * M + c * 8;
        *(float4*)&oext[o]     = make_float4(acc[0], acc[1], acc[2], acc[3]);
        *(float4*)&oext[o + 4] = make_float4(acc[4], acc[5], acc[6], acc[7]);
    }
}

// ---------------- launch -----------------------------------------------------
extern "C" void kernel_launch(void* const* d_in, const int* in_sizes, int n_in,
                              void* d_out, int out_size)
{
    const float* x  = (const float*)d_in[0];
    const void*  ei = d_in[1];
    const float* W1 = (const float*)d_in[2];
    const float* b1 = (const float*)d_in[3];
    const float* W2 = (const float*)d_in[4];
    const float* b2 = (const float*)d_in[5];
    const float* W3 = (const float*)d_in[6];
    const float* b3 = (const float*)d_in[7];
    float* out = (float*)d_out;

    const int N = NN;
    const int E = in_sizes[1] / 2;
    const int n4 = N * (DH / 4);
    const int SM_BYTES = 2 * BUFSH * 2;   // 61440

    cudaFuncSetAttribute(k_mgemm, cudaFuncAttributeMaxDynamicSharedMemorySize,
                         SM_BYTES);

    dim3 tg_h((N + 127) / 128, DH / 128);    // 391 x 2
    dim3 tg_o((N + 127) / 128, DOUT / 128);  // 391 x 1

    const bool par = (g_side != nullptr) && (g_ev_fork != nullptr)
                  && (g_ev_join != nullptr);

    if (par) {
        cudaEventRecord(g_ev_fork, 0);
        cudaStreamWaitEvent(g_side, g_ev_fork, 0);

        k_prepB<<<(E + 255) / 256, 256, 0, g_side>>>(ei, E);
        k_scan <<<1, 1024, 0, g_side>>>();
        k_fill <<<(E + 255) / 256, 256, 0, g_side>>>(ei, E);
        cudaEventRecord(g_ev_join, g_side);

        k_prepA<<<(n4 + 255) / 256, 256>>>(W1, W2, W3, x, n4);
        k_mgemm<<<tg_h, 256, SM_BYTES>>>(N, DH, 0);

        cudaStreamWaitEvent(0, g_ev_join, 0);
    } else {
        k_prepA<<<(n4 + 255) / 256, 256>>>(W1, W2, W3, x, n4);
        k_prepB<<<(E + 255) / 256, 256>>>(ei, E);
        k_scan <<<1, 1024>>>();
        k_fill <<<(E + 255) / 256, 256>>>(ei, E);
        k_mgemm<<<tg_h, 256, SM_BYTES>>>(N, DH, 0);
    }

    k_agg  <<<NN / 4, 128>>>(b1, out, DH, 0);

    k_mgemm<<<tg_h, 256, SM_BYTES>>>(N, DH, 65536);
    k_agg  <<<NN / 4, 128>>>(b2, out, DH, 0);

    k_mgemm<<<tg_o, 256, SM_BYTES>>>(N, DOUT, 131072);
    k_agg  <<<NN / 8, 128>>>(b3, out, DOUT, 1);
}